// round 12
// baseline (speedup 1.0000x reference)
#include <cuda_runtime.h>
#include <cuda_fp16.h>
#include <cstdint>

// ContinousActionDecoder, filter-and-rescue, 512-thread warp-specialized:
//  warps 0-7 consumers (hh-only fp16 mma.sync + screening + rare emit),
//  warps 8-15 producers (cp.async stage -> unit-norm fp16 frags).
//  DOUBLE-buffered stage, 2 cp.async groups in flight -> each load gets
//  ~2 tile-times before convert (no DRAM stall on the critical path).
//  Dynamic per-query thresholds (g_seedkey) seeded by exact prepass,
//  tightened by emissions. Phase 2 rescores candidates exactly in fp32.

#define KD      64
#define QMAX    128
#define BM      128
#define TPB     512
#define RSTRIDE 68
#define ARS     36
#define MARGIN  1.5e-3f
#define CAP     (1 << 21)
#define SROWS   32
#define PGRID   148

#define STAGE_BYTES (BM * RSTRIDE * 4)            // 34816
#define FRAG_BYTES  (BM * ARS * 4)                // 18432
#define OFF_STAGE 0                               // 2 buffers
#define OFF_FRAG  (2 * STAGE_BYTES)               // 69632 (2 buffers)
#define OFF_B     (OFF_FRAG + 2 * FRAG_BYTES)     // 106496
#define B_BYTES   (4 * 16 * 32 * 8)               // 16384
#define OFF_INVB  (OFF_B + B_BYTES)               // 122880
#define OFF_TF    (OFF_INVB + 512)                // 123392
#define SMEM_TOTAL (OFF_TF + 512)                 // 123904

__device__ unsigned long long g_best[QMAX];       // static zero-init
__device__ unsigned int g_seedkey[QMAX];
__device__ int g_ccnt;
__device__ unsigned long long g_cand[CAP];

__device__ __forceinline__ unsigned int fkey(float f) {
    unsigned int u = __float_as_uint(f);
    return (u & 0x80000000u) ? ~u : (u | 0x80000000u);
}
__device__ __forceinline__ float unfkey(unsigned int k) {
    unsigned int u = (k & 0x80000000u) ? (k ^ 0x80000000u) : ~k;
    return __uint_as_float(u);
}
__device__ __forceinline__ uint32_t smem_u32(const void* p) {
    uint32_t a;
    asm("{ .reg .u64 t; cvta.to.shared.u64 t, %1; cvt.u32.u64 %0, t; }"
        : "=r"(a) : "l"(p));
    return a;
}
__device__ __forceinline__ void cpa16(uint32_t s, const void* g) {
    asm volatile("cp.async.cg.shared.global [%0], [%1], 16;" :: "r"(s), "l"(g));
}
__device__ __forceinline__ uint32_t h2pack(float x0, float x1) {
    uint32_t r;
    asm("cvt.rn.f16x2.f32 %0, %1, %2;" : "=r"(r) : "f"(x1), "f"(x0));
    return r;
}
#define MMA_F16(d, a0,a1,a2,a3, b0,b1) \
    asm volatile("mma.sync.aligned.m16n8k16.row.col.f32.f16.f16.f32 " \
        "{%0,%1,%2,%3}, {%4,%5,%6,%7}, {%8,%9}, {%0,%1,%2,%3};" \
        : "+f"((d)[0]), "+f"((d)[1]), "+f"((d)[2]), "+f"((d)[3]) \
        : "r"(a0), "r"(a1), "r"(a2), "r"(a3), "r"(b0), "r"(b1))

#define EMIT_IF(cond, q, row, s) do {                                   \
    if (cond) {                                                         \
        atomicMax(&g_seedkey[(q)], fkey(s));                            \
        int _idx = atomicAdd(&g_ccnt, 1);                               \
        if (_idx < CAP)                                                 \
            g_cand[_idx] = ((unsigned long long)(unsigned)(q) << 32) |  \
                           (unsigned long long)(unsigned)(row);         \
    }                                                                   \
} while (0)

// ---------------- prepass: exact sample scores -> per-query seed ----------
__global__ void __launch_bounds__(256)
prepass(const float* __restrict__ actions, const float* __restrict__ pred,
        int N, int Q)
{
    __shared__ float qn[QMAX * KD];
    __shared__ float rows[SROWS * KD];
    __shared__ float rinv[SROWS];
    __shared__ float qinv[QMAX];
    __shared__ unsigned int skey[QMAX];

    const int tid = threadIdx.x;
    if (tid < QMAX) {
        float iv = 0.f;
        if (tid < Q) {
            float ss = 0.f;
            for (int k = 0; k < KD; ++k) {
                float v = pred[tid * KD + k];
                ss = fmaf(v, v, ss);
            }
            iv = (ss > 1e-30f) ? rsqrtf(ss) : 0.f;
        }
        qinv[tid] = iv;
        skey[tid] = 0u;
    }
    __syncthreads();
    for (int i = tid; i < QMAX * KD; i += 256) {
        int q = i >> 6, k = i & 63;
        qn[i] = (q < Q) ? pred[q * KD + k] * qinv[q] : 0.f;
    }
    const long long total = (long long)PGRID * SROWS;
    for (int i = tid; i < SROWS * 16; i += 256) {
        int r = i >> 4, k4 = i & 15;
        long long si = (long long)blockIdx.x * SROWS + r;
        long long gr = si * N / total;
        if (gr >= N) gr = N - 1;
        *(float4*)&rows[r * KD + k4 * 4] =
            ((const float4*)actions)[gr * (KD / 4) + k4];
    }
    __syncthreads();
    if (tid < SROWS) {
        float ss = 0.f;
        for (int k = 0; k < KD; ++k) {
            float v = rows[tid * KD + k];
            ss = fmaf(v, v, ss);
        }
        rinv[tid] = (ss > 1e-30f) ? rsqrtf(ss) : 0.f;
    }
    __syncthreads();

    const int rl = tid >> 3;
    const int qg = tid & 7;
    float4 rv[16];
#pragma unroll
    for (int k = 0; k < 16; ++k) rv[k] = *(const float4*)&rows[rl * KD + k * 4];
    const float ri = rinv[rl];
#pragma unroll
    for (int j = 0; j < 16; ++j) {
        int q = qg + j * 8;
        const float4* qp = (const float4*)&qn[q * KD];
        float dot = 0.f;
#pragma unroll
        for (int k = 0; k < 16; ++k) {
            float4 b = qp[k];
            dot = fmaf(rv[k].x, b.x, dot);
            dot = fmaf(rv[k].y, b.y, dot);
            dot = fmaf(rv[k].z, b.z, dot);
            dot = fmaf(rv[k].w, b.w, dot);
        }
        if (q < Q) atomicMax(&skey[q], fkey(dot * ri));
    }
    __syncthreads();
    if (tid < QMAX && tid < Q) atomicMax(&g_seedkey[tid], skey[tid]);
}

// ---------------- phase 1 -------------------------------------------------
// 256 producer threads: 8 x 16B chunks each; ALWAYS commits a group
// (possibly empty) so cp.async group accounting stays deterministic.
__device__ __forceinline__ void stage_commit(uint32_t dst, const float4* g4,
                                             long long tile, long long ntiles,
                                             int N, int p)
{
    if (tile < ntiles) {
#pragma unroll
        for (int i = 0; i < 8; ++i) {
            int j = p + i * 256;
            int row = j >> 4, k4 = j & 15;
            long long gr = tile * BM + row;
            if (gr >= N) gr = N - 1;
            cpa16(dst + (uint32_t)(row * RSTRIDE + k4 * 4) * 4u,
                  g4 + gr * (KD / 4) + k4);
        }
    }
    asm volatile("cp.async.commit_group;" ::: "memory");
}

// producer convert: thread p handles half a row (r = p>>1, half = p&1)
__device__ __forceinline__ void convert_half(const float* stg, char* smem,
                                             uint32_t fb, int p)
{
    const int r = p >> 1, h = p & 1;
    const float4* rp = (const float4*)(stg + r * RSTRIDE + h * 32);
    float4 x[8];
    float ss = 0.f;
#pragma unroll
    for (int i = 0; i < 8; ++i) {
        x[i] = rp[i];
        ss = fmaf(x[i].x, x[i].x, ss);
        ss = fmaf(x[i].y, x[i].y, ss);
        ss = fmaf(x[i].z, x[i].z, ss);
        ss = fmaf(x[i].w, x[i].w, ss);
    }
    ss += __shfl_xor_sync(0xffffffffu, ss, 1);
    float inv = (ss > 1e-30f) ? rsqrtf(ss) : 0.f;
    uint32_t* hp = (uint32_t*)(smem + fb) + r * ARS + h * 16;
#pragma unroll
    for (int j = 0; j < 4; ++j) {
        float4 a = x[2 * j];
        float4 b = x[2 * j + 1];
        uint4 hv;
        hv.x = h2pack(a.x * inv, a.y * inv);
        hv.y = h2pack(a.z * inv, a.w * inv);
        hv.z = h2pack(b.x * inv, b.y * inv);
        hv.w = h2pack(b.z * inv, b.w * inv);
        *(uint4*)&hp[j * 4] = hv;
    }
}

extern "C" __global__ void __launch_bounds__(TPB, 1)
sim_argmax(const float* __restrict__ actions, const float* __restrict__ pred,
           int N, int Q)
{
    extern __shared__ char smem[];
    const uint32_t sb = smem_u32(smem);
    float* stage = (float*)smem;
    float* invb  = (float*)(smem + OFF_INVB);
    float* tf_s  = (float*)(smem + OFF_TF);

    const int tid  = threadIdx.x;
    const int lane = tid & 31;
    const int w    = tid >> 5;
    const bool producer = (tid >= 256);
    const int p = tid & 255;

    if (tid < 128) {
        float iv = 0.f;
        if (tid < Q) {
            float ss = 0.f;
            for (int k = 0; k < KD; ++k) {
                float v = pred[tid * KD + k];
                ss = fmaf(v, v, ss);
            }
            iv = (ss > 1e-30f) ? rsqrtf(ss) : 0.f;
        }
        invb[tid] = iv;
        tf_s[tid] = (tid < Q) ? (unfkey(g_seedkey[tid]) - MARGIN) : 3.4e38f;
    }
    __syncthreads();

    // B fragments once: [ks][nt][lane] -> uint2 {bh(k0,k1), bh(k+8)}
#pragma unroll
    for (int i = 0; i < 4; ++i) {
        int slot = tid + i * TPB;
        int ks = slot >> 9;
        int nt = (slot >> 5) & 15;
        int l  = slot & 31;
        int q  = nt * 8 + (l >> 2);
        int k0 = ks * 16 + (l & 3) * 2;
        float iv = invb[q];
        float x0 = 0.f, x1 = 0.f, x2 = 0.f, x3 = 0.f;
        if (q < Q) {
            x0 = pred[q * KD + k0]     * iv;
            x1 = pred[q * KD + k0 + 1] * iv;
            x2 = pred[q * KD + k0 + 8] * iv;
            x3 = pred[q * KD + k0 + 9] * iv;
        }
        uint2 v;
        v.x = h2pack(x0, x1);
        v.y = h2pack(x2, x3);
        *(uint2*)(smem + OFF_B + slot * 8) = v;
    }

    const long long ntiles = ((long long)N + BM - 1) / BM;
    const long long G = gridDim.x;
    const long long t0 = blockIdx.x;
    const float4* g4 = (const float4*)actions;

    // prologue: queue loads for t0 (buf0) and t0+G (buf1); convert t0;
    // then queue t0+2G into buf0. Every load gets >= 2 tile-times.
    if (producer) {
        stage_commit(sb + OFF_STAGE,               g4, t0,     ntiles, N, p);
        stage_commit(sb + OFF_STAGE + STAGE_BYTES, g4, t0 + G, ntiles, N, p);
        if (t0 < ntiles) {
            asm volatile("cp.async.wait_group 1;" ::: "memory");
            asm volatile("bar.sync 1, 256;" ::: "memory");
            convert_half(stage, smem, OFF_FRAG, p);
            asm volatile("bar.sync 1, 256;" ::: "memory");
        }
        stage_commit(sb + OFF_STAGE, g4, t0 + 2 * G, ntiles, N, p);
    }
    __syncthreads();

    float tfr0[16], tfr1[16];
    if (!producer) {
#pragma unroll
        for (int j = 0; j < 16; ++j) {
            int q0 = j * 8 + (lane & 3) * 2;
            tfr0[j] = tf_s[q0];
            tfr1[j] = tf_s[q0 + 1];
        }
    }

    long long tile = t0;
    int it = 0;
    for (; tile < ntiles; tile += G, ++it) {
        if (!producer) {
            if ((it & 15) == 15) {       // periodic threshold refresh
#pragma unroll
                for (int j = 0; j < 16; ++j) {
                    int q0 = j * 8 + (lane & 3) * 2;
                    tfr0[j] = fmaxf(tfr0[j], unfkey(g_seedkey[q0])     - MARGIN);
                    tfr1[j] = fmaxf(tfr1[j], unfkey(g_seedkey[q0 + 1]) - MARGIN);
                }
            }
            const uint32_t* ah = (const uint32_t*)(smem + OFF_FRAG +
                                 (uint32_t)(it & 1) * FRAG_BYTES);
            const int rw = lane >> 2, c4 = lane & 3;
            const int R  = w * 16 + rw;          // consumer warp owns 16 rows

#pragma unroll
            for (int hf = 0; hf < 2; ++hf) {
                float d[8][4];
#pragma unroll
                for (int n = 0; n < 8; ++n)
#pragma unroll
                    for (int c = 0; c < 4; ++c) d[n][c] = 0.f;

#pragma unroll
                for (int ks = 0; ks < 4; ++ks) {
                    int b0 = R * ARS + ks * 8 + c4;
                    int b8 = (R + 8) * ARS + ks * 8 + c4;
                    uint32_t a0 = ah[b0],     a1 = ah[b8];
                    uint32_t a2 = ah[b0 + 4], a3 = ah[b8 + 4];
#pragma unroll
                    for (int n = 0; n < 8; ++n) {
                        uint2 b = *(const uint2*)(smem + OFF_B +
                                  (((ks * 16 + hf * 8 + n) * 32 + lane) << 3));
                        MMA_F16(d[n], a0, a1, a2, a3, b.x, b.y);
                    }
                }

                // branch-free screening over this hf's 32 values
                float mx = -3.4e38f;
#pragma unroll
                for (int n = 0; n < 8; ++n) {
                    int j = hf * 8 + n;
                    float t0f = tfr0[j], t1f = tfr1[j];
                    float m01 = fmaxf(d[n][0] - t0f, d[n][1] - t1f);
                    float m23 = fmaxf(d[n][2] - t0f, d[n][3] - t1f);
                    mx = fmaxf(mx, fmaxf(m01, m23));
                }
                if (__any_sync(0xffffffffu, mx >= 0.f)) {
                    long long r0 = tile * BM + R;
                    bool ok0 = (r0 < N), ok1 = (r0 + 8 < N);
#pragma unroll
                    for (int n = 0; n < 8; ++n) {
                        int j = hf * 8 + n;
                        int q0 = j * 8 + (lane & 3) * 2;
                        float t0f = tfr0[j], t1f = tfr1[j];
                        EMIT_IF(ok0 && d[n][0] >= t0f, q0,     r0,     d[n][0]);
                        EMIT_IF(ok0 && d[n][1] >= t1f, q0 + 1, r0,     d[n][1]);
                        EMIT_IF(ok1 && d[n][2] >= t0f, q0,     r0 + 8, d[n][2]);
                        EMIT_IF(ok1 && d[n][3] >= t1f, q0 + 1, r0 + 8, d[n][3]);
                    }
                }
            }
        } else {
            // convert tile it+1 from stage[(it+1)&1] (load has had ~2 tiles),
            // then queue load of tile it+3 into the same stage buffer.
            long long tc = tile + G;
            if (tc < ntiles) {
                asm volatile("cp.async.wait_group 1;" ::: "memory");
                asm volatile("bar.sync 1, 256;" ::: "memory");
                convert_half(stage + ((it + 1) & 1) * (BM * RSTRIDE), smem,
                             OFF_FRAG + (uint32_t)((it + 1) & 1) * FRAG_BYTES, p);
                asm volatile("bar.sync 1, 256;" ::: "memory");
            }
            stage_commit(sb + OFF_STAGE + (uint32_t)((it + 1) & 1) * STAGE_BYTES,
                         g4, tile + 3 * G, ntiles, N, p);
        }
        __syncthreads();
    }
}

// ---------------- phase 2: exact rescore ----------------------------------
extern "C" __global__ void rescore(const float* __restrict__ actions,
                                   const float* __restrict__ pred, int N)
{
    int total = g_ccnt;
    if (total > CAP) total = CAP;
    const int stride = gridDim.x * blockDim.x;
    for (int i = blockIdx.x * blockDim.x + threadIdx.x; i < total; i += stride) {
        unsigned long long c = g_cand[i];
        int q = (int)(c >> 32);
        unsigned row = (unsigned)c;
        const float4* a = (const float4*)(actions + (size_t)row * KD);
        const float4* b = (const float4*)(pred + (size_t)q * KD);
        float dot = 0.f, na = 0.f;
#pragma unroll
        for (int j = 0; j < 16; ++j) {
            float4 av = a[j], bv = b[j];
            dot = fmaf(av.x, bv.x, dot);
            dot = fmaf(av.y, bv.y, dot);
            dot = fmaf(av.z, bv.z, dot);
            dot = fmaf(av.w, bv.w, dot);
            na = fmaf(av.x, av.x, na);
            na = fmaf(av.y, av.y, na);
            na = fmaf(av.z, av.z, na);
            na = fmaf(av.w, av.w, na);
        }
        float s = dot / sqrtf(fmaxf(na, 1e-30f));
        unsigned long long pk = ((unsigned long long)fkey(s) << 32) |
                                (unsigned long long)(~row);
        atomicMax(&g_best[q], pk);
    }
}

__global__ void gather(const float* __restrict__ actions,
                       float* __restrict__ out, int Q) {
    int q = blockIdx.x;
    int t = threadIdx.x;
    unsigned int idx = ~(unsigned int)(g_best[q] & 0xFFFFFFFFull);
    out[(size_t)q * KD + t] = actions[(size_t)idx * KD + t];
    __syncthreads();
    if (t == 0) {
        g_best[q] = 0ull;
        g_seedkey[q] = 0u;
        if (q == 0) g_ccnt = 0;
    }
}

extern "C" void kernel_launch(void* const* d_in, const int* in_sizes, int n_in,
                              void* d_out, int out_size) {
    int ip = 0, ia = 1;
    if (n_in >= 2 && in_sizes[0] > in_sizes[1]) { ip = 1; ia = 0; }
    const float* pred    = (const float*)d_in[ip];
    const float* actions = (const float*)d_in[ia];
    int Q = in_sizes[ip] / KD;
    if (Q > QMAX) Q = QMAX;
    int N = in_sizes[ia] / KD;

    cudaFuncSetAttribute(sim_argmax,
                         cudaFuncAttributeMaxDynamicSharedMemorySize,
                         SMEM_TOTAL);

    prepass<<<PGRID, 256>>>(actions, pred, N, Q);
    sim_argmax<<<148, TPB, SMEM_TOTAL>>>(actions, pred, N, Q);
    rescore<<<148, 256>>>(actions, pred, N);
    gather<<<Q, KD>>>(actions, (float*)d_out, Q);
}

// round 13
// speedup vs baseline: 1.2679x; 1.2679x over previous
#include <cuda_runtime.h>
#include <cuda_fp16.h>
#include <cstdint>

// ContinousActionDecoder, filter-and-rescue, barrier-free hot loop:
//  Each warp loads its own MMA A-fragments directly from GMEM (LDG.64,
//  full-sector), computes row norms via 4-lane shuffles, packs unit-norm
//  fp16 frags in registers, and runs hh-only m16n8k16 against smem-resident
//  query frags. No producers, no cp.async, no __syncthreads in the loop.
//  2 CTAs/SM (small smem), dynamic per-query thresholds, exact rescore.

#define KD      64
#define QMAX    128
#define BM      128
#define TPB     256
#define GRIDX   296
#define MARGIN  1.5e-3f
#define CAP     (1 << 21)
#define SROWS   32
#define PGRID   148

__device__ unsigned long long g_best[QMAX];       // static zero-init
__device__ unsigned int g_seedkey[QMAX];
__device__ int g_ccnt;
__device__ unsigned long long g_cand[CAP];

__device__ __forceinline__ unsigned int fkey(float f) {
    unsigned int u = __float_as_uint(f);
    return (u & 0x80000000u) ? ~u : (u | 0x80000000u);
}
__device__ __forceinline__ float unfkey(unsigned int k) {
    unsigned int u = (k & 0x80000000u) ? (k ^ 0x80000000u) : ~k;
    return __uint_as_float(u);
}
__device__ __forceinline__ uint32_t h2pack(float lo, float hi) {
    uint32_t r;
    asm("cvt.rn.f16x2.f32 %0, %1, %2;" : "=r"(r) : "f"(hi), "f"(lo));
    return r;
}
#define MMA_F16(d, a0,a1,a2,a3, b0,b1) \
    asm volatile("mma.sync.aligned.m16n8k16.row.col.f32.f16.f16.f32 " \
        "{%0,%1,%2,%3}, {%4,%5,%6,%7}, {%8,%9}, {%0,%1,%2,%3};" \
        : "+f"((d)[0]), "+f"((d)[1]), "+f"((d)[2]), "+f"((d)[3]) \
        : "r"(a0), "r"(a1), "r"(a2), "r"(a3), "r"(b0), "r"(b1))

#define EMIT_IF(cond, q, row, s) do {                                   \
    if (cond) {                                                         \
        atomicMax(&g_seedkey[(q)], fkey(s));                            \
        int _idx = atomicAdd(&g_ccnt, 1);                               \
        if (_idx < CAP)                                                 \
            g_cand[_idx] = ((unsigned long long)(unsigned)(q) << 32) |  \
                           (unsigned long long)(unsigned)(row);         \
    }                                                                   \
} while (0)

// ---------------- prepass: exact sample scores -> per-query seed ----------
__global__ void __launch_bounds__(256)
prepass(const float* __restrict__ actions, const float* __restrict__ pred,
        int N, int Q)
{
    __shared__ float qn[QMAX * KD];
    __shared__ float rows[SROWS * KD];
    __shared__ float rinv[SROWS];
    __shared__ float qinv[QMAX];
    __shared__ unsigned int skey[QMAX];

    const int tid = threadIdx.x;
    if (tid < QMAX) {
        float iv = 0.f;
        if (tid < Q) {
            float ss = 0.f;
            for (int k = 0; k < KD; ++k) {
                float v = pred[tid * KD + k];
                ss = fmaf(v, v, ss);
            }
            iv = (ss > 1e-30f) ? rsqrtf(ss) : 0.f;
        }
        qinv[tid] = iv;
        skey[tid] = 0u;
    }
    __syncthreads();
    for (int i = tid; i < QMAX * KD; i += 256) {
        int q = i >> 6, k = i & 63;
        qn[i] = (q < Q) ? pred[q * KD + k] * qinv[q] : 0.f;
    }
    const long long total = (long long)PGRID * SROWS;
    for (int i = tid; i < SROWS * 16; i += 256) {
        int r = i >> 4, k4 = i & 15;
        long long si = (long long)blockIdx.x * SROWS + r;
        long long gr = si * N / total;
        if (gr >= N) gr = N - 1;
        *(float4*)&rows[r * KD + k4 * 4] =
            ((const float4*)actions)[gr * (KD / 4) + k4];
    }
    __syncthreads();
    if (tid < SROWS) {
        float ss = 0.f;
        for (int k = 0; k < KD; ++k) {
            float v = rows[tid * KD + k];
            ss = fmaf(v, v, ss);
        }
        rinv[tid] = (ss > 1e-30f) ? rsqrtf(ss) : 0.f;
    }
    __syncthreads();

    const int rl = tid >> 3;
    const int qg = tid & 7;
    float4 rv[16];
#pragma unroll
    for (int k = 0; k < 16; ++k) rv[k] = *(const float4*)&rows[rl * KD + k * 4];
    const float ri = rinv[rl];
#pragma unroll
    for (int j = 0; j < 16; ++j) {
        int q = qg + j * 8;
        const float4* qp = (const float4*)&qn[q * KD];
        float dot = 0.f;
#pragma unroll
        for (int k = 0; k < 16; ++k) {
            float4 b = qp[k];
            dot = fmaf(rv[k].x, b.x, dot);
            dot = fmaf(rv[k].y, b.y, dot);
            dot = fmaf(rv[k].z, b.z, dot);
            dot = fmaf(rv[k].w, b.w, dot);
        }
        if (q < Q) atomicMax(&skey[q], fkey(dot * ri));
    }
    __syncthreads();
    if (tid < QMAX && tid < Q) atomicMax(&g_seedkey[tid], skey[tid]);
}

// ---------------- phase 1: barrier-free screened MMA ----------------------
// thread (rw = lane>>2, c4 = lane&3) loads rows {R, R+8} at k = 8m + 2c4
// (float2 index 4m + c4) -> exactly its own A-fragment elements.
__device__ __forceinline__ void load_rows(float2* L0, float2* L1,
                                          const float* __restrict__ actions,
                                          long long tile, int Rb, int rw,
                                          int c4, int N)
{
    long long r0 = tile * BM + Rb + rw;
    long long r1 = r0 + 8;
    if (r0 >= N) r0 = N - 1;
    if (r1 >= N) r1 = N - 1;
    const float2* p0 = (const float2*)(actions + r0 * KD) + c4;
    const float2* p1 = (const float2*)(actions + r1 * KD) + c4;
#pragma unroll
    for (int m = 0; m < 8; ++m) {
        L0[m] = p0[4 * m];
        L1[m] = p1[4 * m];
    }
}

extern "C" __global__ void __launch_bounds__(TPB, 2)
sim_argmax(const float* __restrict__ actions, const float* __restrict__ pred,
           int N, int Q)
{
    __shared__ float invb[QMAX];
    __shared__ float tf_s[QMAX];
    __shared__ uint2 Bf[2048];                 // 16 KB query frags

    const int tid  = threadIdx.x;
    const int lane = tid & 31;
    const int w    = tid >> 5;
    const int rw   = lane >> 2;
    const int c4   = lane & 3;
    const int Rb   = w * 16;

    // query inverse norms + initial thresholds from global seed
    if (tid < QMAX) {
        float iv = 0.f;
        if (tid < Q) {
            float ss = 0.f;
            for (int k = 0; k < KD; ++k) {
                float v = pred[tid * KD + k];
                ss = fmaf(v, v, ss);
            }
            iv = (ss > 1e-30f) ? rsqrtf(ss) : 0.f;
        }
        invb[tid] = iv;
        tf_s[tid] = (tid < Q) ? (unfkey(g_seedkey[tid]) - MARGIN) : 3.4e38f;
    }
    __syncthreads();

    // B fragments once: [ks][nt][lane] -> uint2 {bh(k0,k1), bh(k+8)}
#pragma unroll
    for (int i = 0; i < 8; ++i) {
        int slot = tid + i * TPB;              // 0..2047
        int ks = slot >> 9;
        int nt = (slot >> 5) & 15;
        int l  = slot & 31;
        int q  = nt * 8 + (l >> 2);
        int k0 = ks * 16 + (l & 3) * 2;
        float iv = invb[q];
        float x0 = 0.f, x1 = 0.f, x2 = 0.f, x3 = 0.f;
        if (q < Q) {
            x0 = pred[q * KD + k0]     * iv;
            x1 = pred[q * KD + k0 + 1] * iv;
            x2 = pred[q * KD + k0 + 8] * iv;
            x3 = pred[q * KD + k0 + 9] * iv;
        }
        uint2 v;
        v.x = h2pack(x0, x1);
        v.y = h2pack(x2, x3);
        Bf[slot] = v;
    }
    __syncthreads();                            // last barrier before loop

    const long long ntiles = ((long long)N + BM - 1) / BM;
    long long tile = blockIdx.x;

    float2 L0[8], L1[8];
    if (tile < ntiles) load_rows(L0, L1, actions, tile, Rb, rw, c4, N);

    int it = 0;
    for (; tile < ntiles; tile += GRIDX, ++it) {
        // ---- row norms (exact fp32) via 4-lane shuffle reduce
        float ss0 = 0.f, ss1 = 0.f;
#pragma unroll
        for (int m = 0; m < 8; ++m) {
            ss0 = fmaf(L0[m].x, L0[m].x, ss0);
            ss0 = fmaf(L0[m].y, L0[m].y, ss0);
            ss1 = fmaf(L1[m].x, L1[m].x, ss1);
            ss1 = fmaf(L1[m].y, L1[m].y, ss1);
        }
        ss0 += __shfl_xor_sync(0xffffffffu, ss0, 1);
        ss0 += __shfl_xor_sync(0xffffffffu, ss0, 2);
        ss1 += __shfl_xor_sync(0xffffffffu, ss1, 1);
        ss1 += __shfl_xor_sync(0xffffffffu, ss1, 2);
        float inv0 = (ss0 > 1e-30f) ? rsqrtf(ss0) : 0.f;
        float inv1 = (ss1 > 1e-30f) ? rsqrtf(ss1) : 0.f;

        // ---- pack unit-norm fp16 A-frags in registers
        uint32_t a[4][4];
#pragma unroll
        for (int ks = 0; ks < 4; ++ks) {
            a[ks][0] = h2pack(L0[2 * ks].x * inv0,     L0[2 * ks].y * inv0);
            a[ks][1] = h2pack(L1[2 * ks].x * inv1,     L1[2 * ks].y * inv1);
            a[ks][2] = h2pack(L0[2 * ks + 1].x * inv0, L0[2 * ks + 1].y * inv0);
            a[ks][3] = h2pack(L1[2 * ks + 1].x * inv1, L1[2 * ks + 1].y * inv1);
        }

        // ---- prefetch next tile's rows (hides DRAM under MMA loop)
        long long tn = tile + GRIDX;
        load_rows(L0, L1, actions, (tn < ntiles) ? tn : tile, Rb, rw, c4, N);

        // ---- periodic threshold refresh (racing, monotone-safe)
        if ((it & 15) == 15) {
            for (int j = lane; j < QMAX; j += 32)
                tf_s[j] = fmaxf(tf_s[j], unfkey(g_seedkey[j]) - MARGIN);
        }

        const long long r0g = tile * BM + Rb + rw;
        const bool ok0 = (r0g < N), ok1 = (r0g + 8 < N);

#pragma unroll
        for (int hf = 0; hf < 2; ++hf) {
            float d[8][4];
#pragma unroll
            for (int n = 0; n < 8; ++n)
#pragma unroll
                for (int c = 0; c < 4; ++c) d[n][c] = 0.f;

#pragma unroll
            for (int ks = 0; ks < 4; ++ks) {
#pragma unroll
                for (int n = 0; n < 8; ++n) {
                    uint2 b = Bf[(ks * 16 + hf * 8 + n) * 32 + lane];
                    MMA_F16(d[n], a[ks][0], a[ks][1], a[ks][2], a[ks][3],
                            b.x, b.y);
                }
            }

            // branch-free screening over this hf's 32 values
            float mx = -3.4e38f;
#pragma unroll
            for (int n = 0; n < 8; ++n) {
                int j = hf * 8 + n;
                float t0f = tf_s[j * 8 + 2 * c4];
                float t1f = tf_s[j * 8 + 2 * c4 + 1];
                float m01 = fmaxf(d[n][0] - t0f, d[n][1] - t1f);
                float m23 = fmaxf(d[n][2] - t0f, d[n][3] - t1f);
                mx = fmaxf(mx, fmaxf(m01, m23));
            }
            if (__any_sync(0xffffffffu, mx >= 0.f)) {
#pragma unroll
                for (int n = 0; n < 8; ++n) {
                    int j = hf * 8 + n;
                    int q0 = j * 8 + 2 * c4;
                    float t0f = tf_s[q0];
                    float t1f = tf_s[q0 + 1];
                    EMIT_IF(ok0 && d[n][0] >= t0f, q0,     r0g,     d[n][0]);
                    EMIT_IF(ok0 && d[n][1] >= t1f, q0 + 1, r0g,     d[n][1]);
                    EMIT_IF(ok1 && d[n][2] >= t0f, q0,     r0g + 8, d[n][2]);
                    EMIT_IF(ok1 && d[n][3] >= t1f, q0 + 1, r0g + 8, d[n][3]);
                }
            }
        }
    }
}

// ---------------- phase 2: exact rescore ----------------------------------
extern "C" __global__ void rescore(const float* __restrict__ actions,
                                   const float* __restrict__ pred, int N)
{
    int total = g_ccnt;
    if (total > CAP) total = CAP;
    const int stride = gridDim.x * blockDim.x;
    for (int i = blockIdx.x * blockDim.x + threadIdx.x; i < total; i += stride) {
        unsigned long long c = g_cand[i];
        int q = (int)(c >> 32);
        unsigned row = (unsigned)c;
        const float4* a = (const float4*)(actions + (size_t)row * KD);
        const float4* b = (const float4*)(pred + (size_t)q * KD);
        float dot = 0.f, na = 0.f;
#pragma unroll
        for (int j = 0; j < 16; ++j) {
            float4 av = a[j], bv = b[j];
            dot = fmaf(av.x, bv.x, dot);
            dot = fmaf(av.y, bv.y, dot);
            dot = fmaf(av.z, bv.z, dot);
            dot = fmaf(av.w, bv.w, dot);
            na = fmaf(av.x, av.x, na);
            na = fmaf(av.y, av.y, na);
            na = fmaf(av.z, av.z, na);
            na = fmaf(av.w, av.w, na);
        }
        float s = dot / sqrtf(fmaxf(na, 1e-30f));
        unsigned long long pk = ((unsigned long long)fkey(s) << 32) |
                                (unsigned long long)(~row);
        atomicMax(&g_best[q], pk);
    }
}

__global__ void gather(const float* __restrict__ actions,
                       float* __restrict__ out, int Q) {
    int q = blockIdx.x;
    int t = threadIdx.x;
    unsigned int idx = ~(unsigned int)(g_best[q] & 0xFFFFFFFFull);
    out[(size_t)q * KD + t] = actions[(size_t)idx * KD + t];
    __syncthreads();
    if (t == 0) {
        g_best[q] = 0ull;
        g_seedkey[q] = 0u;
        if (q == 0) g_ccnt = 0;
    }
}

extern "C" void kernel_launch(void* const* d_in, const int* in_sizes, int n_in,
                              void* d_out, int out_size) {
    int ip = 0, ia = 1;
    if (n_in >= 2 && in_sizes[0] > in_sizes[1]) { ip = 1; ia = 0; }
    const float* pred    = (const float*)d_in[ip];
    const float* actions = (const float*)d_in[ia];
    int Q = in_sizes[ip] / KD;
    if (Q > QMAX) Q = QMAX;
    int N = in_sizes[ia] / KD;

    prepass<<<PGRID, 256>>>(actions, pred, N, Q);
    sim_argmax<<<GRIDX, TPB>>>(actions, pred, N, Q);
    rescore<<<148, 256>>>(actions, pred, N);
    gather<<<Q, KD>>>(actions, (float*)d_out, Q);
}